// round 8
// baseline (speedup 1.0000x reference)
#include <cuda_runtime.h>
#include <math.h>
#include <stdint.h>

#define NNODES 4096
#define C_MATS 32
#define TOTAL (32 * 4096 * 16)
#define NB 3
#define WARPS 8
#define ITERS 4
#define NCTA (TOTAL / (32 * WARPS * ITERS))   // 2048

typedef unsigned int u32;
typedef unsigned long long u64;

// ---------------------------------------------------------------------------
// Device scratch (no cudaMalloc allowed)
// ---------------------------------------------------------------------------
__device__ float g_graphs[C_MATS * 64];
__device__ int   g_class[NNODES];
// L1/L2 weight fragments (mma B layout, k16n8), pre-split hi/lo:
__device__ u64 g_F1[3 * 4 * 8 * 2 * 32];   // [blk][kc(4)][nt(8)][term][lane] K=64,N=64
__device__ u64 g_F2[3 * 4 * 2 * 32];       // [blk][kc(4)][term][lane]        K=64,N=8
// Per-class folded L0 weights: Weff[cls][blk] rows = [W0[:4] | G@W0[4:12] | b0 | 0,0,0]
// as k16n8 B fragments: [cls][blk][nt(8)][term(2)][lane]
__device__ u64 g_WB0[C_MATS * 3 * 8 * 2 * 32];

// ---------------------------------------------------------------------------
// helpers
// ---------------------------------------------------------------------------
#define CVT_BF16X2_F32(result, a, b) \
    asm("cvt.rn.satfinite.bf16x2.f32 %0, %1, %2;" : "=r"(result) : "f"(b), "f"(a))

__device__ __forceinline__ void split2(float e, float o, u32& hi, u32& lo) {
    u32 h; CVT_BF16X2_F32(h, e, o);
    float he = __uint_as_float(h << 16);
    float ho = __uint_as_float(h & 0xFFFF0000u);
    float le = e - he, lf = o - ho;
    u32 l; CVT_BF16X2_F32(l, le, lf);
    hi = h; lo = l;
}

__device__ __forceinline__ void frag_split(float w0, float w1, float w2, float w3,
                                           u64& hi, u64& lo) {
    u32 h0; CVT_BF16X2_F32(h0, w0, w1);
    u32 h1; CVT_BF16X2_F32(h1, w2, w3);
    float r0 = w0 - __uint_as_float(h0 << 16);
    float r1 = w1 - __uint_as_float(h0 & 0xFFFF0000u);
    float r2 = w2 - __uint_as_float(h1 << 16);
    float r3 = w3 - __uint_as_float(h1 & 0xFFFF0000u);
    u32 l0; CVT_BF16X2_F32(l0, r0, r1);
    u32 l1; CVT_BF16X2_F32(l1, r2, r3);
    hi = (u64)h0 | ((u64)h1 << 32);
    lo = (u64)l0 | ((u64)l1 << 32);
}

// m16n8k16 bf16 mma, D accumulates in place (fp32)
__device__ __forceinline__ void mma16816(float* d, const u32* a, u32 b0, u32 b1) {
    asm volatile(
        "mma.sync.aligned.m16n8k16.row.col.f32.bf16.bf16.f32 "
        "{%0,%1,%2,%3}, {%4,%5,%6,%7}, {%8,%9}, {%0,%1,%2,%3};"
        : "+f"(d[0]), "+f"(d[1]), "+f"(d[2]), "+f"(d[3])
        : "r"(a[0]), "r"(a[1]), "r"(a[2]), "r"(a[3]), "r"(b0), "r"(b1));
}

__device__ __forceinline__ float ftanh(float x) {
    float e = __expf(2.0f * x);
    return __fdividef(e - 1.0f, e + 1.0f);
}

// ---------------------------------------------------------------------------
// Complex double helpers (eig-free graphs kernel)
// ---------------------------------------------------------------------------
struct cd { double x, y; };
__device__ __forceinline__ cd cmul(cd a, cd b) { return cd{a.x*b.x - a.y*b.y, a.x*b.y + a.y*b.x}; }
__device__ __forceinline__ cd csub(cd a, cd b) { return cd{a.x - b.x, a.y - b.y}; }
__device__ __forceinline__ cd cdivc(cd a, cd b) {
    double d = b.x*b.x + b.y*b.y;
    return cd{(a.x*b.x + a.y*b.y)/d, (a.y*b.x - a.x*b.y)/d};
}

// ---------------------------------------------------------------------------
// Kernel 1: G[c] = A * p(A)  (validated: rel_err ~2.4e-6)
// ---------------------------------------------------------------------------
__global__ void __launch_bounds__(64) graphs_kernel(const float* __restrict__ koop)
{
    int c = blockIdx.x;
    int t = threadIdx.x;
    int i = t >> 3, j = t & 7;

    __shared__ double A[64], M[64], T[64];
    __shared__ double coef[9];
    __shared__ cd zsh[8];
    __shared__ cd dcoef[8];
    __shared__ cd Mc[64], Tc[64];

    A[t] = (double)koop[c * 64 + t];
    __syncthreads();

    if (t == 0) { double tr = 0; for (int d = 0; d < 8; d++) tr += A[d * 9]; coef[1] = -tr; }
    M[t] = A[t];
    __syncthreads();
    for (int k = 2; k <= 8; k++) {
        T[t] = M[t] + ((i == j) ? coef[k - 1] : 0.0);
        __syncthreads();
        double s = 0;
        #pragma unroll
        for (int d = 0; d < 8; d++) s += A[i * 8 + d] * T[d * 8 + j];
        M[t] = s;
        __syncthreads();
        if (t == 0) { double tr = 0; for (int d = 0; d < 8; d++) tr += M[d * 9]; coef[k] = -tr / (double)k; }
        __syncthreads();
    }

    if (t < 8) {
        cd z = cd{1.0, 0.0};
        cd base = cd{0.4, 0.9};
        for (int p = 0; p <= t; p++) z = cmul(z, base);
        const unsigned msk = 0xFFu;
        for (int iter = 0; iter < 300; iter++) {
            cd p = cd{1.0, 0.0};
            #pragma unroll
            for (int k = 1; k <= 8; k++) { p = cmul(p, z); p.x += coef[k]; }
            cd den = cd{1.0, 0.0};
            #pragma unroll
            for (int j2 = 0; j2 < 8; j2++) {
                double zx = __shfl_sync(msk, z.x, j2);
                double zy = __shfl_sync(msk, z.y, j2);
                if (j2 != t) den = cmul(den, csub(z, cd{zx, zy}));
            }
            cd corr = cdivc(p, den);
            z = csub(z, corr);
            double cn = corr.x * corr.x + corr.y * corr.y;
            unsigned done = __ballot_sync(msk, cn < 1e-26);
            if (done == 0xFFu) break;
        }
        zsh[t] = z;
    }
    __syncthreads();

    if (t == 0) {
        double m[8]; int any = 0;
        for (int r = 0; r < 8; r++) {
            double zx = zsh[r].x + 1e-10, zy = zsh[r].y + 1e-10;
            double a = sqrt(zx * zx + zy * zy);
            m[r] = (a <= 1.1 && a >= 0.9) ? 1.0 : 0.0;
            if (m[r] != 0.0) any = 1;
        }
        if (!any) for (int r = 0; r < 8; r++) m[r] = 1.0;
        cd f[8];
        for (int r = 0; r < 8; r++) f[r] = cd{m[r], 0.0};
        for (int lev = 1; lev < 8; lev++)
            for (int r = 7; r >= lev; r--)
                f[r] = cdivc(csub(f[r], f[r - 1]), csub(zsh[r], zsh[r - lev]));
        for (int r = 0; r < 8; r++) dcoef[r] = f[r];
    }
    __syncthreads();

    Mc[t] = (i == j) ? dcoef[7] : cd{0.0, 0.0};
    __syncthreads();
    for (int k = 6; k >= 0; k--) {
        cd s = cd{0.0, 0.0};
        #pragma unroll
        for (int d = 0; d < 8; d++) { double a = A[i * 8 + d]; cd mm = Mc[d * 8 + j]; s.x += a * mm.x; s.y += a * mm.y; }
        cd zk = zsh[k]; cd mij = Mc[t];
        s.x -= zk.x * mij.x - zk.y * mij.y;
        s.y -= zk.x * mij.y + zk.y * mij.x;
        if (i == j) { s.x += dcoef[k].x; s.y += dcoef[k].y; }
        Tc[t] = s;
        __syncthreads();
        Mc[t] = Tc[t];
        __syncthreads();
    }

    double g = 0;
    #pragma unroll
    for (int d = 0; d < 8; d++) g += A[i * 8 + d] * Mc[d * 8 + j].x;
    g_graphs[c * 64 + t] = (float)g;
}

// ---------------------------------------------------------------------------
// Kernel 2: per-node community argmax
// ---------------------------------------------------------------------------
__global__ void __launch_bounds__(128) class_kernel(const float* __restrict__ community)
{
    int n = blockIdx.x * blockDim.x + threadIdx.x;
    if (n >= NNODES) return;
    const float* r = community + n * 32;
    float best = r[0]; int bi = 0;
    #pragma unroll
    for (int cc = 1; cc < 32; cc++) { float v = r[cc]; if (v > best) { best = v; bi = cc; } }
    g_class[n] = bi;
}

// ---------------------------------------------------------------------------
// Kernel 2b: L1/L2 weight fragments (hi/lo bf16, mma B layout)
// ---------------------------------------------------------------------------
__global__ void __launch_bounds__(128) prep_kernel(
    const float* __restrict__ W1, const float* __restrict__ W2)
{
    int g = blockIdx.x * blockDim.x + threadIdx.x;
    int stride = gridDim.x * blockDim.x;

    for (int i = g; i < 3072; i += stride) {
        int lane = i & 31; int t = i >> 5; int nt = t & 7; int t2 = t >> 3;
        int kc = t2 & 3, blk = t2 >> 2;
        int k0 = kc * 16 + (lane & 3) * 2, n = nt * 8 + (lane >> 2);
        const float* W = W1 + blk * 4096;
        float w0 = W[k0 * 64 + n];
        float w1 = W[(k0 + 1) * 64 + n];
        float w2 = W[(k0 + 8) * 64 + n];
        float w3 = W[(k0 + 9) * 64 + n];
        u64 hi, lo; frag_split(w0, w1, w2, w3, hi, lo);
        g_F1[(((blk * 4 + kc) * 8 + nt) * 2 + 0) * 32 + lane] = hi;
        g_F1[(((blk * 4 + kc) * 8 + nt) * 2 + 1) * 32 + lane] = lo;
    }
    for (int i = g; i < 384; i += stride) {
        int lane = i & 31; int t = i >> 5; int kc = t & 3, blk = t >> 2;
        int k0 = kc * 16 + (lane & 3) * 2, n = lane >> 2;
        const float* W = W2 + blk * 512;
        float w0 = W[k0 * 8 + n];
        float w1 = W[(k0 + 1) * 8 + n];
        float w2 = W[(k0 + 8) * 8 + n];
        float w3 = W[(k0 + 9) * 8 + n];
        u64 hi, lo; frag_split(w0, w1, w2, w3, hi, lo);
        g_F2[((blk * 4 + kc) * 2 + 0) * 32 + lane] = hi;
        g_F2[((blk * 4 + kc) * 2 + 1) * 32 + lane] = lo;
    }
}

// ---------------------------------------------------------------------------
// Kernel 2c: per-class folded L0 weights.
// Weff[cls][blk] (16x64): rows 0-3 = W0[:4] (current-x1 slot),
// rows 4-11 = G[cls] @ W0[4:12] (original-x slot), row 12 = b0, rows 13-15 = 0.
// Must run AFTER graphs_kernel.
// ---------------------------------------------------------------------------
__global__ void __launch_bounds__(128) prep2_kernel(
    const float* __restrict__ W0, const float* __restrict__ b0)
{
    int idx = blockIdx.x * blockDim.x + threadIdx.x;   // 3072 = 32cls*3blk*32lane
    if (idx >= 3072) return;
    int lane = idx & 31; int t = idx >> 5;
    int blk = t % 3, cls = t / 3;
    int k0 = (lane & 3) * 2;
    const float* G  = g_graphs + cls * 64;
    const float* W  = W0 + blk * 768;    // [12][64]
    const float* bb = b0 + blk * 64;

    for (int nt = 0; nt < 8; nt++) {
        int n = nt * 8 + (lane >> 2);
        float w[4];
        int ks[4] = {k0, k0 + 1, k0 + 8, k0 + 9};
        #pragma unroll
        for (int q = 0; q < 4; q++) {
            int k = ks[q]; float v;
            if (k < 4) v = W[k * 64 + n];
            else if (k < 12) {
                int d = k - 4; v = 0.f;
                for (int e = 0; e < 8; e++) v += G[d * 8 + e] * W[(4 + e) * 64 + n];
            }
            else if (k == 12) v = bb[n];
            else v = 0.f;
            w[q] = v;
        }
        u64 hi, lo; frag_split(w[0], w[1], w[2], w[3], hi, lo);
        g_WB0[(((cls * 3 + blk) * 8 + nt) * 2 + 0) * 32 + lane] = hi;
        g_WB0[(((cls * 3 + blk) * 8 + nt) * 2 + 1) * 32 + lane] = lo;
    }
}

// ---------------------------------------------------------------------------
// Kernel 3: HMMA main pass.
// L0 A = [x1_cur(4), x_orig(8), 1, 0,0,0]; B = Weff[cls] from gmem (L2-hit,
// class-uniform per m16 tile). cond GEMV + L0 bias eliminated.
// x_orig bf16 hi/lo split once per iter; single m16 row-group per phase.
// ---------------------------------------------------------------------------
// smem layout (bytes)
#define SM_F1    0                        // 49152
#define SM_F2    49152                    // 6144
#define SM_BIAS1 55296                    // 768
#define SM_BIAS2 56064                    // 96 (+pad to 128)
#define SM_SCR   56192                    // 8 warps * 2048
#define SMEM_TOTAL (SM_SCR + WARPS * 2048)   // 72576

__global__ void __launch_bounds__(256, 2) prior_kernel(
    const float* __restrict__ latent,
    const float* __restrict__ b1, const float* __restrict__ b2,
    float* __restrict__ out)
{
    extern __shared__ char smc[];
    const int tid = threadIdx.x;

    // ---- stage L1/L2 fragments + biases into smem ----
    {
        u64* dst1 = (u64*)(smc + SM_F1);
        u64* dst2 = (u64*)(smc + SM_F2);
        for (int i = tid; i < 6144; i += 256) dst1[i] = g_F1[i];
        for (int i = tid; i < 768;  i += 256) dst2[i] = g_F2[i];
        float* sb1 = (float*)(smc + SM_BIAS1);
        float* sb2 = (float*)(smc + SM_BIAS2);
        if (tid < 192) sb1[tid] = b1[tid];
        if (tid < 24)  sb2[tid] = b2[tid];
    }
    __syncthreads();

    const int lane = tid & 31;
    const int wld  = tid >> 5;
    const int qr = lane >> 2;       // frag row within 8-row half
    const int qc = lane & 3;        // column quad
    char* scr = smc + SM_SCR + wld * 2048;
    char* s_xo = scr;               // 32 rows * 32B: [hi0..hi3 | lo0..lo3]
    char* s_x1 = scr + 1024;        // 16 rows * 16B (tile-local, current x1)
    char* s_o  = scr + 1280;        // 16 rows * 32B (tile-local)

    const char* f1l = smc + SM_F1 + (size_t)lane * 8;
    const char* f2l = smc + SM_F2 + (size_t)lane * 8;

    for (int it = 0; it < ITERS; it++) {
        const int rbase = ((blockIdx.x * WARPS + wld) * ITERS + it) * 32;
        const int row = rbase + lane;

        const float4* lp = (const float4*)(latent + (size_t)row * 8);
        float4 xa = lp[0];
        float4 xb = lp[1];

        __syncwarp();   // prior iter's s_xo reads complete
        // ---- stage x_orig bf16 hi/lo pairs (own row), once per iter ----
        {
            u32 h0, l0, h1, l1, h2, l2, h3, l3;
            split2(xa.x, xa.y, h0, l0);
            split2(xa.z, xa.w, h1, l1);
            split2(xb.x, xb.y, h2, l2);
            split2(xb.z, xb.w, h3, l3);
            *(uint4*)(s_xo + lane * 32)      = make_uint4(h0, h1, h2, h3);
            *(uint4*)(s_xo + lane * 32 + 16) = make_uint4(l0, l1, l2, l3);
        }
        __syncwarp();

        float logdet = 0.f;

        for (int h = 0; h < 2; h++) {
            const bool owner = ((lane >> 4) == h);
            const int cls = g_class[((rbase + h * 16) >> 4) & (NNODES - 1)];
            const u64* wb = g_WB0 + ((size_t)(cls * 3) << 9) + lane;   // +blk*512, entries j*32
            const char* xo_qr  = s_xo + (h * 16 + qr) * 32;
            const char* xo_qr8 = s_xo + (h * 16 + qr + 8) * 32;

            for (int blk = 0; blk < NB; blk++) {
                const bool odd = (blk == 1);
                if (owner) *(float4*)(s_x1 + (lane & 15) * 16) = odd ? xb : xa;
                __syncwarp();

                // ---- L0 A fragments: [x1_cur | x_orig | 1 | 0] ----
                u32 A0h[4], A0l[4];
                if (qc < 2) {
                    float2 p0 = *(const float2*)(s_x1 + qr * 16 + qc * 8);
                    float2 p1 = *(const float2*)(s_x1 + (qr + 8) * 16 + qc * 8);
                    split2(p0.x, p0.y, A0h[0], A0l[0]);
                    split2(p1.x, p1.y, A0h[1], A0l[1]);
                    A0h[2] = *(const u32*)(xo_qr  + (2 + qc) * 4);
                    A0l[2] = *(const u32*)(xo_qr  + 16 + (2 + qc) * 4);
                    A0h[3] = *(const u32*)(xo_qr8 + (2 + qc) * 4);
                    A0l[3] = *(const u32*)(xo_qr8 + 16 + (2 + qc) * 4);
                } else {
                    int p = qc - 2;           // x_orig pair 0 or 1
                    A0h[0] = *(const u32*)(xo_qr  + p * 4);
                    A0l[0] = *(const u32*)(xo_qr  + 16 + p * 4);
                    A0h[1] = *(const u32*)(xo_qr8 + p * 4);
                    A0l[1] = *(const u32*)(xo_qr8 + 16 + p * 4);
                    u32 cone = (qc == 2) ? 0x00003F80u : 0u;   // {bf16 1.0, 0} at k12,13
                    A0h[2] = cone; A0h[3] = cone;
                    A0l[2] = 0;    A0l[3] = 0;
                }

                // ---- L0 mma (B from gmem, class-folded, bias included) ----
                float D[8][4];
                #pragma unroll
                for (int nt = 0; nt < 8; nt++)
                    #pragma unroll
                    for (int q = 0; q < 4; q++) D[nt][q] = 0.f;
                const u64* wp = wb + ((size_t)blk << 9);
                #pragma unroll
                for (int nt = 0; nt < 8; nt++) {
                    u64 vh = __ldg(wp + (nt * 2) * 32);
                    u64 vl = __ldg(wp + (nt * 2 + 1) * 32);
                    mma16816(D[nt], A0h, (u32)vh, (u32)(vh >> 32));
                    mma16816(D[nt], A0h, (u32)vl, (u32)(vl >> 32));
                    mma16816(D[nt], A0l, (u32)vh, (u32)(vh >> 32));
                }

                // ---- L0 epilogue: h1 = relu(D) (bias folded) -> A frags ----
                u32 Ah[16], Al[16];
                #pragma unroll
                for (int nt = 0; nt < 8; nt++) {
                    int base = (nt >> 1) * 4 + (nt & 1) * 2;
                    float v0 = fmaxf(D[nt][0], 0.f);
                    float v1 = fmaxf(D[nt][1], 0.f);
                    float v2 = fmaxf(D[nt][2], 0.f);
                    float v3 = fmaxf(D[nt][3], 0.f);
                    split2(v0, v1, Ah[base],     Al[base]);
                    split2(v2, v3, Ah[base + 1], Al[base + 1]);
                }

                // ---- L1 mma: K=64 x N=64 ----
                #pragma unroll
                for (int nt = 0; nt < 8; nt++)
                    #pragma unroll
                    for (int q = 0; q < 4; q++) D[nt][q] = 0.f;
                #pragma unroll
                for (int kc = 0; kc < 4; kc++) {
                    #pragma unroll
                    for (int nt = 0; nt < 8; nt++) {
                        const char* fp = f1l + (size_t)((blk * 4 + kc) * 8 + nt) * 512;
                        u64 vh = *(const u64*)fp;
                        u64 vl = *(const u64*)(fp + 256);
                        mma16816(D[nt], &Ah[kc * 4], (u32)vh, (u32)(vh >> 32));
                        mma16816(D[nt], &Ah[kc * 4], (u32)vl, (u32)(vl >> 32));
                        mma16816(D[nt], &Al[kc * 4], (u32)vh, (u32)(vh >> 32));
                    }
                }

                // ---- L1 epilogue ----
                #pragma unroll
                for (int nt = 0; nt < 8; nt++) {
                    float2 bv = *(const float2*)(smc + SM_BIAS1 + blk * 256 + nt * 32 + qc * 8);
                    int base = (nt >> 1) * 4 + (nt & 1) * 2;
                    float v0 = fmaxf(D[nt][0] + bv.x, 0.f);
                    float v1 = fmaxf(D[nt][1] + bv.y, 0.f);
                    float v2 = fmaxf(D[nt][2] + bv.x, 0.f);
                    float v3 = fmaxf(D[nt][3] + bv.y, 0.f);
                    split2(v0, v1, Ah[base],     Al[base]);
                    split2(v2, v3, Ah[base + 1], Al[base + 1]);
                }

                // ---- L2 mma: K=64 x N=8 ----
                float O[4] = {0.f, 0.f, 0.f, 0.f};
                #pragma unroll
                for (int kc = 0; kc < 4; kc++) {
                    const char* fp = f2l + (size_t)(blk * 4 + kc) * 512;
                    u64 vh = *(const u64*)fp;
                    u64 vl = *(const u64*)(fp + 256);
                    mma16816(O, &Ah[kc * 4], (u32)vh, (u32)(vh >> 32));
                    mma16816(O, &Ah[kc * 4], (u32)vl, (u32)(vl >> 32));
                    mma16816(O, &Al[kc * 4], (u32)vh, (u32)(vh >> 32));
                }

                // ---- distribute o to tile rows ----
                {
                    float2 bv = *(const float2*)(smc + SM_BIAS2 + blk * 32 + qc * 8);
                    *(float2*)(s_o + qr * 32 + qc * 8)       = make_float2(O[0] + bv.x, O[1] + bv.y);
                    *(float2*)(s_o + (qr + 8) * 32 + qc * 8) = make_float2(O[2] + bv.x, O[3] + bv.y);
                }
                __syncwarp();

                // ---- per-row affine update (owner lanes) ----
                if (owner) {
                    int r = lane & 15;
                    float4 oA = *(const float4*)(s_o + r * 32);
                    float4 oB = *(const float4*)(s_o + r * 32 + 16);
                    float s0 = ftanh(oA.x), s1 = ftanh(oA.y), s2 = ftanh(oA.z), s3 = ftanh(oA.w);
                    logdet += s0 + s1 + s2 + s3;
                    float e0 = __expf(s0), e1 = __expf(s1), e2 = __expf(s2), e3 = __expf(s3);
                    if (odd) {
                        xa.x = xa.x*e0 + oB.x; xa.y = xa.y*e1 + oB.y;
                        xa.z = xa.z*e2 + oB.z; xa.w = xa.w*e3 + oB.w;
                    } else {
                        xb.x = xb.x*e0 + oB.x; xb.y = xb.y*e1 + oB.y;
                        xb.z = xb.z*e2 + oB.z; xb.w = xb.w*e3 + oB.w;
                    }
                }
                __syncwarp();
            }
        }

        float ss = xa.x*xa.x + xa.y*xa.y + xa.z*xa.z + xa.w*xa.w
                 + xb.x*xb.x + xb.y*xb.y + xb.z*xb.z + xb.w*xb.w;
        out[row] = -0.5f * ss - 7.3515082656373815f + logdet;
    }
}

// ---------------------------------------------------------------------------
extern "C" void kernel_launch(void* const* d_in, const int* in_sizes, int n_in,
                              void* d_out, int out_size)
{
    const float* latent    = (const float*)d_in[0];
    const float* koop      = (const float*)d_in[1];
    const float* community = (const float*)d_in[2];
    const float* W0 = (const float*)d_in[3];
    const float* b0 = (const float*)d_in[4];
    const float* W1 = (const float*)d_in[5];
    const float* b1 = (const float*)d_in[6];
    const float* W2 = (const float*)d_in[7];
    const float* b2 = (const float*)d_in[8];
    float* out = (float*)d_out;

    cudaFuncSetAttribute(prior_kernel, cudaFuncAttributeMaxDynamicSharedMemorySize, SMEM_TOTAL);

    graphs_kernel<<<C_MATS, 64>>>(koop);
    class_kernel<<<32, 128>>>(community);
    prep_kernel<<<27, 128>>>(W1, W2);
    prep2_kernel<<<24, 128>>>(W0, b0);     // after graphs_kernel (reads g_graphs)
    prior_kernel<<<NCTA, 256, SMEM_TOTAL>>>(latent, b1, b2, out);
}